// round 13
// baseline (speedup 1.0000x reference)
#include <cuda_runtime.h>
#include <cuda_fp16.h>
#include <cstdint>

typedef unsigned int uint;

#define NC 184
#define NHIST 24
#define NPRED 24
#define NF 17
#define NHID 32
#define NROWS 94208
#define SEQ 48
#define GRID 736
#define NGATE 128

// dynamic smem layout (bytes)
#define SM_BHI  0        // B fp16 tile: [kc][n] 16B rows, 10*2048
#define SM_AHI  20480    // A fp16: [kc][row] 16B rows, 10*2048
#define SM_HBUF 40960    // h fp32 [128][33]
#define SM_WOUT 57856
#define SM_BOUT 57984
#define SM_SIZE 58112

// ---------------- device-global staged weights --------------------------------
__device__ __half g_B[10240];        // fused B tile, fp16, ldmatrix layout, n = g*32+j
__device__ float  g_Wf[NGATE*41];    // fused Wih@Win, row-direct (row = g*32+j)
__device__ float  g_BG[NGATE];       // fused bias, row-direct
__device__ float  g_WOUT[NHID];
__device__ float  g_BOUT[1];

__global__ void prep1(const float* __restrict__ Win, const float* __restrict__ bin,
                      const float* __restrict__ Wih, const float* __restrict__ bih,
                      const float* __restrict__ bhh,
                      const float* __restrict__ Wout, const float* __restrict__ bout)
{
    int idx = blockIdx.x*blockDim.x + threadIdx.x;
    if (idx < NGATE*41) {
        int row = idx / 41, k = idx % 41;
        float s = 0.f;
        #pragma unroll 8
        for (int m = 0; m < NHID; m++) s += Wih[row*NHID + m] * Win[m*41 + k];
        g_Wf[idx] = s;
    }
    if (idx < NGATE) {
        float s = bih[idx] + bhh[idx];
        #pragma unroll 8
        for (int m = 0; m < NHID; m++) s += Wih[idx*NHID + m] * bin[m];
        g_BG[idx] = s;
    }
    if (idx < NHID) g_WOUT[idx] = Wout[idx];
    if (idx == 0) g_BOUT[0] = bout[0];
}

// B[k][n], n = g*32+j (gate-planar): k<41 fused W; k=41 bias; 42..47 zero; 48..79 Whh.
// Stored [k>>3][n][k&7] fp16 (16B per (kc,n) row for ldmatrix).
__global__ void prep2(const float* __restrict__ Whh)
{
    int idx = blockIdx.x*blockDim.x + threadIdx.x;
    if (idx >= NGATE*80) return;
    int n = idx / 80, k = idx % 80;
    float v = 0.f;
    if (k < 41)       v = g_Wf[n*41 + k];
    else if (k == 41) v = g_BG[n];
    else if (k >= 48) v = Whh[n*NHID + (k - 48)];
    g_B[(k >> 3)*1024 + n*8 + (k & 7)] = __float2half_rn(v);
}

// ---------------- PTX helpers ---------------------------------------------------
__device__ __forceinline__ uint smem_u32(const void* p) {
    uint a; asm("{ .reg .u64 t; cvta.to.shared.u64 t, %1; cvt.u32.u64 %0, t; }"
                : "=r"(a) : "l"(p));
    return a;
}

#define LDSM4(r0, r1, r2, r3, addr) \
    asm volatile("ldmatrix.sync.aligned.m8n8.x4.shared.b16 {%0,%1,%2,%3}, [%4];" \
        : "=r"(r0), "=r"(r1), "=r"(r2), "=r"(r3) : "r"(addr))

#define LDSM2(r0, r1, addr) \
    asm volatile("ldmatrix.sync.aligned.m8n8.x2.shared.b16 {%0,%1}, [%2];" \
        : "=r"(r0), "=r"(r1) : "r"(addr))

#define MMA16816(d, a, b) \
    asm volatile("mma.sync.aligned.m16n8k16.row.col.f32.f16.f16.f32 " \
        "{%0,%1,%2,%3}, {%4,%5,%6,%7}, {%8,%9}, {%0,%1,%2,%3};" \
        : "+f"((d)[0]), "+f"((d)[1]), "+f"((d)[2]), "+f"((d)[3]) \
        : "r"((a)[0]), "r"((a)[1]), "r"((a)[2]), "r"((a)[3]), \
          "r"((b)[0]), "r"((b)[1]))

// fp32 pair -> fp16x2 (a in low half)
__device__ __forceinline__ uint packh2(float a, float b) {
    __half2 h2 = __floats2half2_rn(a, b);
    return *reinterpret_cast<uint*>(&h2);
}

// MUFU.TANH-based activations: 1 MUFU each
__device__ __forceinline__ float ftanh_(float v) {
    float y; asm("tanh.approx.f32 %0, %1;" : "=f"(y) : "f"(v));
    return y;
}
__device__ __forceinline__ float fsigmoid(float v) {
    float y; asm("tanh.approx.f32 %0, %1;" : "=f"(y) : "f"(v*0.5f));
    return fmaf(0.5f, y, 0.5f);
}

// ---------------- main kernel: HMMA LSTM, single-pass fp16 ----------------------
__global__ void __launch_bounds__(128) lstm_hmma_kernel(
    const float* __restrict__ pm25,
    const float* __restrict__ feature,
    float* __restrict__ out)
{
    extern __shared__ char smem[];
    const uint sb = smem_u32(smem);
    const int tid = threadIdx.x;
    const int w = tid >> 5, lane = tid & 31;

    // stage B + vectors
    {
        const uint4* s = (const uint4*)g_B;
        uint4* d = (uint4*)(smem + SM_BHI);
        #pragma unroll
        for (int i = 0; i < 10; i++) d[i*128 + tid] = s[i*128 + tid];
    }
    if (tid < NHID) ((float*)(smem + SM_WOUT))[tid] = g_WOUT[tid];
    if (tid == 0)   *(float*)(smem + SM_BOUT) = g_BOUT[0];
    {
        uint4 z = make_uint4(0,0,0,0);
        #pragma unroll
        for (int kc = 6; kc < 10; kc++)
            ((uint4*)(smem + SM_AHI))[kc*128 + tid] = z;   // h=0
    }
    __syncthreads();

    // per-thread row state (thread = row for I/O, A-pack, pred)
    const int r = blockIdx.x*128 + tid;
    const int b = r / NC;
    const int c = r - b*NC;

    float xn[NHIST];
    #pragma unroll
    for (int t = 0; t < NHIST; t++) xn[t] = pm25[(size_t)r*NHIST + t];
    // c-state: cell (row', j) owned by the thread whose d-regs produce it
    float cst[32];
    #pragma unroll
    for (int i = 0; i < 32; i++) cst[i] = 0.0f;

    const float* fptr = feature + (((size_t)b*SEQ + NHIST)*NC + c)*NF;
    float* optr = out + ((size_t)b*NPRED)*NC + c;

    const float* sW  = (const float*)(smem + SM_WOUT);
    const float boutv = *(const float*)(smem + SM_BOUT);
    float* hbuf = (float*)(smem + SM_HBUF);

    // ldmatrix lane base addresses
    const uint rowA   = (uint)(w<<5) + (lane & 7) + (((lane >> 3) & 1) << 3);
    const uint aHiB   = sb + SM_AHI + rowA*16 + ((uint)(lane >> 4) & 1)*2048;
    const uint bBase  = sb + SM_BHI + (uint)(lane & 7)*16 + (((uint)(lane >> 3) & 1))*2048;

    // epilogue cell coordinates for this lane
    const int q = lane & 3;
    const int rbase = (w<<5) + (lane>>2);   // + mt*16 + rh*8

    #pragma unroll 1
    for (int s = 0; s < NPRED; s++) {
        // ---- build v = [xn | feat | 1(bias) | 0pad] fp16 ----
        float ft[NF];
        #pragma unroll
        for (int f = 0; f < NF; f++) ft[f] = fptr[f];
        fptr += (size_t)NC*NF;

        uint vh[24];
        #pragma unroll
        for (int p = 0; p < 12; p++) vh[p] = packh2(xn[2*p], xn[2*p+1]);
        #pragma unroll
        for (int p = 0; p < 8; p++) vh[12+p] = packh2(ft[2*p], ft[2*p+1]);
        vh[20] = packh2(ft[16], 1.0f);                // k40 = feat16, k41 = 1.0 (bias col)
        vh[21] = vh[22] = vh[23] = 0u;

        #pragma unroll
        for (int kc = 0; kc < 6; kc++)
            ((uint4*)(smem + SM_AHI))[kc*128 + tid] =
                make_uint4(vh[4*kc], vh[4*kc+1], vh[4*kc+2], vh[4*kc+3]);
        __syncwarp();

        // ---- hoisted A fragment loads (shared across all 16 n-tiles) ----
        uint afh[2][5][4];
        #pragma unroll
        for (int mt = 0; mt < 2; mt++)
            #pragma unroll
            for (int kt = 0; kt < 5; kt++)
                LDSM4(afh[mt][kt][0], afh[mt][kt][1], afh[mt][kt][2], afh[mt][kt][3],
                      aHiB + mt*256 + kt*4096);

        // ---- per n-tile: 4 gate-planes accumulate, then shuffle-free epilogue ----
        #pragma unroll
        for (int nt = 0; nt < 4; nt++) {
            float d[4][2][4];
            #pragma unroll
            for (int g = 0; g < 4; g++) {
                #pragma unroll
                for (int mt = 0; mt < 2; mt++)
                    #pragma unroll
                    for (int i = 0; i < 4; i++) d[g][mt][i] = 0.f;
                #pragma unroll
                for (int kt = 0; kt < 5; kt++) {
                    uint bf[2];
                    LDSM2(bf[0], bf[1], bBase + g*512 + nt*128 + kt*4096);
                    MMA16816(d[g][0], afh[0][kt], bf);
                    MMA16816(d[g][1], afh[1][kt], bf);
                }
            }
            // cells: rows rbase + mt*16 + rh*8 ; j = nt*8 + 2q + t
            #pragma unroll
            for (int mt = 0; mt < 2; mt++)
                #pragma unroll
                for (int rh = 0; rh < 2; rh++)
                    #pragma unroll
                    for (int t = 0; t < 2; t++) {
                        const int dreg = 2*rh + t;
                        const float zi = d[0][mt][dreg];
                        const float zf = d[1][mt][dreg];
                        const float zg = d[2][mt][dreg];
                        const float zo = d[3][mt][dreg];
                        const int ci = ((nt*2 + mt)*2 + rh)*2 + t;
                        const float cn = fmaf(fsigmoid(zf), cst[ci],
                                              fsigmoid(zi)*ftanh_(zg));
                        cst[ci] = cn;
                        const float hvv = fsigmoid(zo) * ftanh_(cn);
                        const int row = rbase + (mt<<4) + (rh<<3);
                        const int jj  = (nt<<3) + (q<<1) + t;
                        hbuf[row*33 + jj] = hvv;
                    }
        }
        __syncwarp();

        // ---- per-thread: gather own row's h, pred, pack h into A for next step ----
        float pred = boutv;
        uint hh[16];
        #pragma unroll
        for (int p = 0; p < 16; p++) {
            const float h0 = hbuf[tid*33 + 2*p];
            const float h1 = hbuf[tid*33 + 2*p + 1];
            pred = fmaf(sW[2*p],   h0, pred);
            pred = fmaf(sW[2*p+1], h1, pred);
            hh[p] = packh2(h0, h1);
        }
        #pragma unroll
        for (int kc = 0; kc < 4; kc++)
            ((uint4*)(smem + SM_AHI))[(6+kc)*128 + tid] =
                make_uint4(hh[4*kc], hh[4*kc+1], hh[4*kc+2], hh[4*kc+3]);

        optr[(size_t)s*NC] = pred;
        #pragma unroll
        for (int t = 0; t < NHIST-1; t++) xn[t] = xn[t+1];
        xn[NHIST-1] = pred;
        __syncwarp();
    }
}

// ---------------- launch --------------------------------------------------------
extern "C" void kernel_launch(void* const* d_in, const int* in_sizes, int n_in,
                              void* d_out, int out_size)
{
    const float* pm25    = (const float*)d_in[0];
    const float* feature = (const float*)d_in[1];
    // d_in[2] time_feature: unused
    const float* Win  = (const float*)d_in[3];
    const float* bin  = (const float*)d_in[4];
    const float* Wih  = (const float*)d_in[5];
    const float* Whh  = (const float*)d_in[6];
    const float* bih  = (const float*)d_in[7];
    const float* bhh  = (const float*)d_in[8];
    const float* Wout = (const float*)d_in[9];
    const float* bout = (const float*)d_in[10];
    float* out = (float*)d_out;

    cudaFuncSetAttribute(lstm_hmma_kernel,
                         cudaFuncAttributeMaxDynamicSharedMemorySize, SM_SIZE);

    prep1<<<21, 256>>>(Win, bin, Wih, bih, bhh, Wout, bout);
    prep2<<<40, 256>>>(Whh);
    lstm_hmma_kernel<<<GRID, 128, SM_SIZE>>>(pm25, feature, out);
}

// round 15
// speedup vs baseline: 1.0019x; 1.0019x over previous
#include <cuda_runtime.h>
#include <cuda_fp16.h>
#include <cstdint>

typedef unsigned int uint;

#define NC 184
#define NHIST 24
#define NPRED 24
#define NF 17
#define NHID 32
#define NROWS 94208
#define SEQ 48
#define GRID 736
#define NGATE 128

// dynamic smem layout (bytes)
#define SM_BHI  0        // B fp16 tile: [kc][n] 16B rows, 10*2048
#define SM_AHI  20480    // A fp16: [kc][row] 16B rows, 10*2048
#define SM_HBUF 40960    // h fp32 [128][33]
#define SM_WOUT 57856
#define SM_BOUT 57984
#define SM_SIZE 58112

// ---------------- device-global staged weights --------------------------------
__device__ __half g_B[10240];        // fused B tile, fp16, ldmatrix layout, n = g*32+j
__device__ float  g_Wf[NGATE*41];    // fused Wih@Win, row-direct (row = g*32+j)
__device__ float  g_BG[NGATE];       // fused bias, row-direct
__device__ float  g_WOUT[NHID];
__device__ float  g_BOUT[1];

__global__ void prep1(const float* __restrict__ Win, const float* __restrict__ bin,
                      const float* __restrict__ Wih, const float* __restrict__ bih,
                      const float* __restrict__ bhh,
                      const float* __restrict__ Wout, const float* __restrict__ bout)
{
    int idx = blockIdx.x*blockDim.x + threadIdx.x;
    if (idx < NGATE*41) {
        int row = idx / 41, k = idx % 41;
        float s = 0.f;
        #pragma unroll 8
        for (int m = 0; m < NHID; m++) s += Wih[row*NHID + m] * Win[m*41 + k];
        g_Wf[idx] = s;
    }
    if (idx < NGATE) {
        float s = bih[idx] + bhh[idx];
        #pragma unroll 8
        for (int m = 0; m < NHID; m++) s += Wih[idx*NHID + m] * bin[m];
        g_BG[idx] = s;
    }
    if (idx < NHID) g_WOUT[idx] = Wout[idx];
    if (idx == 0) g_BOUT[0] = bout[0];
}

// B[k][n], n = g*32+j (gate-planar): k<41 fused W; k=41 bias; 42..47 zero; 48..79 Whh.
// Stored [k>>3][n][k&7] fp16 (16B per (kc,n) row for ldmatrix).
__global__ void prep2(const float* __restrict__ Whh)
{
    int idx = blockIdx.x*blockDim.x + threadIdx.x;
    if (idx >= NGATE*80) return;
    int n = idx / 80, k = idx % 80;
    float v = 0.f;
    if (k < 41)       v = g_Wf[n*41 + k];
    else if (k == 41) v = g_BG[n];
    else if (k >= 48) v = Whh[n*NHID + (k - 48)];
    g_B[(k >> 3)*1024 + n*8 + (k & 7)] = __float2half_rn(v);
}

// ---------------- PTX helpers ---------------------------------------------------
__device__ __forceinline__ uint smem_u32(const void* p) {
    uint a; asm("{ .reg .u64 t; cvta.to.shared.u64 t, %1; cvt.u32.u64 %0, t; }"
                : "=r"(a) : "l"(p));
    return a;
}

#define LDSM4(r0, r1, r2, r3, addr) \
    asm volatile("ldmatrix.sync.aligned.m8n8.x4.shared.b16 {%0,%1,%2,%3}, [%4];" \
        : "=r"(r0), "=r"(r1), "=r"(r2), "=r"(r3) : "r"(addr))

#define LDSM2(r0, r1, addr) \
    asm volatile("ldmatrix.sync.aligned.m8n8.x2.shared.b16 {%0,%1}, [%2];" \
        : "=r"(r0), "=r"(r1) : "r"(addr))

#define MMA16816(d, a, b) \
    asm volatile("mma.sync.aligned.m16n8k16.row.col.f32.f16.f16.f32 " \
        "{%0,%1,%2,%3}, {%4,%5,%6,%7}, {%8,%9}, {%0,%1,%2,%3};" \
        : "+f"((d)[0]), "+f"((d)[1]), "+f"((d)[2]), "+f"((d)[3]) \
        : "r"((a)[0]), "r"((a)[1]), "r"((a)[2]), "r"((a)[3]), \
          "r"((b)[0]), "r"((b)[1]))

// fp32 pair -> fp16x2 (a in low half)
__device__ __forceinline__ uint packh2(float a, float b) {
    __half2 h2 = __floats2half2_rn(a, b);
    return *reinterpret_cast<uint*>(&h2);
}

// MUFU.TANH-based activations: 1 MUFU each
__device__ __forceinline__ float ftanh_(float v) {
    float y; asm("tanh.approx.f32 %0, %1;" : "=f"(y) : "f"(v));
    return y;
}
__device__ __forceinline__ float fsigmoid(float v) {
    float y; asm("tanh.approx.f32 %0, %1;" : "=f"(y) : "f"(v*0.5f));
    return fmaf(0.5f, y, 0.5f);
}

// ---------------- main kernel: HMMA LSTM, single-pass fp16 ----------------------
__global__ void __launch_bounds__(128) lstm_hmma_kernel(
    const float* __restrict__ pm25,
    const float* __restrict__ feature,
    float* __restrict__ out)
{
    extern __shared__ char smem[];
    const uint sb = smem_u32(smem);
    const int tid = threadIdx.x;
    const int w = tid >> 5, lane = tid & 31;

    // stage B + vectors
    {
        const uint4* s = (const uint4*)g_B;
        uint4* d = (uint4*)(smem + SM_BHI);
        #pragma unroll
        for (int i = 0; i < 10; i++) d[i*128 + tid] = s[i*128 + tid];
    }
    if (tid < NHID) ((float*)(smem + SM_WOUT))[tid] = g_WOUT[tid];
    if (tid == 0)   *(float*)(smem + SM_BOUT) = g_BOUT[0];
    {
        uint4 z = make_uint4(0,0,0,0);
        #pragma unroll
        for (int kc = 6; kc < 10; kc++)
            ((uint4*)(smem + SM_AHI))[kc*128 + tid] = z;   // h=0
    }
    __syncthreads();

    // per-thread row state (thread = row for I/O, A-pack, pred)
    const int r = blockIdx.x*128 + tid;
    const int b = r / NC;
    const int c = r - b*NC;

    float xn[NHIST];
    #pragma unroll
    for (int t = 0; t < NHIST; t++) xn[t] = pm25[(size_t)r*NHIST + t];
    // c-state: cell (row', j) owned by the thread whose d-regs produce it
    float cst[32];
    #pragma unroll
    for (int i = 0; i < 32; i++) cst[i] = 0.0f;

    const float* fptr = feature + (((size_t)b*SEQ + NHIST)*NC + c)*NF;
    float* optr = out + ((size_t)b*NPRED)*NC + c;

    const float* sW  = (const float*)(smem + SM_WOUT);
    const float boutv = *(const float*)(smem + SM_BOUT);
    float* hbuf = (float*)(smem + SM_HBUF);

    // ldmatrix lane base addresses
    const uint rowA   = (uint)(w<<5) + (lane & 7) + (((lane >> 3) & 1) << 3);
    const uint aHiB   = sb + SM_AHI + rowA*16 + ((uint)(lane >> 4) & 1)*2048;
    const uint bBase  = sb + SM_BHI + (uint)(lane & 7)*16 + (((uint)(lane >> 3) & 1))*2048;

    // epilogue cell coordinates for this lane
    const int q = lane & 3;
    const int rbase = (w<<5) + (lane>>2);   // + mt*16 + rh*8

    #pragma unroll 1
    for (int s = 0; s < NPRED; s++) {
        // ---- build v = [xn | feat | 1(bias) | 0pad] fp16 ----
        float ft[NF];
        #pragma unroll
        for (int f = 0; f < NF; f++) ft[f] = fptr[f];
        fptr += (size_t)NC*NF;

        uint vh[24];
        #pragma unroll
        for (int p = 0; p < 12; p++) vh[p] = packh2(xn[2*p], xn[2*p+1]);
        #pragma unroll
        for (int p = 0; p < 8; p++) vh[12+p] = packh2(ft[2*p], ft[2*p+1]);
        vh[20] = packh2(ft[16], 1.0f);                // k40 = feat16, k41 = 1.0 (bias col)
        vh[21] = vh[22] = vh[23] = 0u;

        #pragma unroll
        for (int kc = 0; kc < 6; kc++)
            ((uint4*)(smem + SM_AHI))[kc*128 + tid] =
                make_uint4(vh[4*kc], vh[4*kc+1], vh[4*kc+2], vh[4*kc+3]);
        __syncwarp();

        // ---- hoisted A fragment loads (shared across all 16 n-tiles) ----
        uint afh[2][5][4];
        #pragma unroll
        for (int mt = 0; mt < 2; mt++)
            #pragma unroll
            for (int kt = 0; kt < 5; kt++)
                LDSM4(afh[mt][kt][0], afh[mt][kt][1], afh[mt][kt][2], afh[mt][kt][3],
                      aHiB + mt*256 + kt*4096);

        // ---- per n-tile: 4 gate-planes accumulate, then shuffle-free epilogue ----
        #pragma unroll
        for (int nt = 0; nt < 4; nt++) {
            float d[4][2][4];
            #pragma unroll
            for (int g = 0; g < 4; g++) {
                #pragma unroll
                for (int mt = 0; mt < 2; mt++)
                    #pragma unroll
                    for (int i = 0; i < 4; i++) d[g][mt][i] = 0.f;
                #pragma unroll
                for (int kt = 0; kt < 5; kt++) {
                    uint bf[2];
                    LDSM2(bf[0], bf[1], bBase + g*512 + nt*128 + kt*4096);
                    MMA16816(d[g][0], afh[0][kt], bf);
                    MMA16816(d[g][1], afh[1][kt], bf);
                }
            }
            // cells: rows rbase + mt*16 + rh*8 ; j = nt*8 + 2q + t
            #pragma unroll
            for (int mt = 0; mt < 2; mt++)
                #pragma unroll
                for (int rh = 0; rh < 2; rh++)
                    #pragma unroll
                    for (int t = 0; t < 2; t++) {
                        const int dreg = 2*rh + t;
                        const float zi = d[0][mt][dreg];
                        const float zf = d[1][mt][dreg];
                        const float zg = d[2][mt][dreg];
                        const float zo = d[3][mt][dreg];
                        const int ci = ((nt*2 + mt)*2 + rh)*2 + t;
                        const float cn = fmaf(fsigmoid(zf), cst[ci],
                                              fsigmoid(zi)*ftanh_(zg));
                        cst[ci] = cn;
                        const float hvv = fsigmoid(zo) * ftanh_(cn);
                        const int row = rbase + (mt<<4) + (rh<<3);
                        const int jj  = (nt<<3) + (q<<1) + t;
                        hbuf[row*33 + jj] = hvv;
                    }
        }
        __syncwarp();

        // ---- per-thread: gather own row's h, pred, pack h into A for next step ----
        float pred = boutv;
        uint hh[16];
        #pragma unroll
        for (int p = 0; p < 16; p++) {
            const float h0 = hbuf[tid*33 + 2*p];
            const float h1 = hbuf[tid*33 + 2*p + 1];
            pred = fmaf(sW[2*p],   h0, pred);
            pred = fmaf(sW[2*p+1], h1, pred);
            hh[p] = packh2(h0, h1);
        }
        #pragma unroll
        for (int kc = 0; kc < 4; kc++)
            ((uint4*)(smem + SM_AHI))[(6+kc)*128 + tid] =
                make_uint4(hh[4*kc], hh[4*kc+1], hh[4*kc+2], hh[4*kc+3]);

        optr[(size_t)s*NC] = pred;
        #pragma unroll
        for (int t = 0; t < NHIST-1; t++) xn[t] = xn[t+1];
        xn[NHIST-1] = pred;
        __syncwarp();
    }
}

// ---------------- launch --------------------------------------------------------
extern "C" void kernel_launch(void* const* d_in, const int* in_sizes, int n_in,
                              void* d_out, int out_size)
{
    const float* pm25    = (const float*)d_in[0];
    const float* feature = (const float*)d_in[1];
    // d_in[2] time_feature: unused
    const float* Win  = (const float*)d_in[3];
    const float* bin  = (const float*)d_in[4];
    const float* Wih  = (const float*)d_in[5];
    const float* Whh  = (const float*)d_in[6];
    const float* bih  = (const float*)d_in[7];
    const float* bhh  = (const float*)d_in[8];
    const float* Wout = (const float*)d_in[9];
    const float* bout = (const float*)d_in[10];
    float* out = (float*)d_out;

    cudaFuncSetAttribute(lstm_hmma_kernel,
                         cudaFuncAttributeMaxDynamicSharedMemorySize, SM_SIZE);

    prep1<<<21, 256>>>(Win, bin, Wih, bih, bhh, Wout, bout);
    prep2<<<40, 256>>>(Whh);
    lstm_hmma_kernel<<<GRID, 128, SM_SIZE>>>(pm25, feature, out);
}

// round 16
// speedup vs baseline: 1.0050x; 1.0031x over previous
#include <cuda_runtime.h>
#include <cuda_fp16.h>
#include <cstdint>

typedef unsigned int uint;

#define NC 184
#define NHIST 24
#define NPRED 24
#define NF 17
#define NHID 32
#define NROWS 94208
#define SEQ 48
#define GRID 736
#define NGATE 128

// dynamic smem layout (bytes)
#define SM_BHI  0        // B fp16 tile: [kc][n] 16B rows, 10*2048
#define SM_AHI  20480    // A fp16: [kc][row] 16B rows, 10*2048
#define SM_HBUF 40960    // h fp32 [128][33]
#define SM_WOUT 57856
#define SM_BOUT 57984
#define SM_SIZE 58112

// ---------------- device-global staged weights --------------------------------
__device__ __half g_B[10240];        // fused B tile, fp16, ldmatrix layout, n = g*32+j
__device__ float  g_Wf[NGATE*41];    // fused Wih@Win, row-direct (row = g*32+j)
__device__ float  g_BG[NGATE];       // fused bias, row-direct
__device__ float  g_WOUT[NHID];
__device__ float  g_BOUT[1];

__global__ void prep1(const float* __restrict__ Win, const float* __restrict__ bin,
                      const float* __restrict__ Wih, const float* __restrict__ bih,
                      const float* __restrict__ bhh,
                      const float* __restrict__ Wout, const float* __restrict__ bout)
{
    int idx = blockIdx.x*blockDim.x + threadIdx.x;
    if (idx < NGATE*41) {
        int row = idx / 41, k = idx % 41;
        float s = 0.f;
        #pragma unroll 8
        for (int m = 0; m < NHID; m++) s += Wih[row*NHID + m] * Win[m*41 + k];
        g_Wf[idx] = s;
    }
    if (idx < NGATE) {
        float s = bih[idx] + bhh[idx];
        #pragma unroll 8
        for (int m = 0; m < NHID; m++) s += Wih[idx*NHID + m] * bin[m];
        g_BG[idx] = s;
    }
    if (idx < NHID) g_WOUT[idx] = Wout[idx];
    if (idx == 0) g_BOUT[0] = bout[0];
}

// B[k][n], n = g*32+j (gate-planar): k<41 fused W; k=41 bias; 42..47 zero; 48..79 Whh.
// Stored [k>>3][n][k&7] fp16 (16B per (kc,n) row for ldmatrix).
__global__ void prep2(const float* __restrict__ Whh)
{
    int idx = blockIdx.x*blockDim.x + threadIdx.x;
    if (idx >= NGATE*80) return;
    int n = idx / 80, k = idx % 80;
    float v = 0.f;
    if (k < 41)       v = g_Wf[n*41 + k];
    else if (k == 41) v = g_BG[n];
    else if (k >= 48) v = Whh[n*NHID + (k - 48)];
    g_B[(k >> 3)*1024 + n*8 + (k & 7)] = __float2half_rn(v);
}

// ---------------- PTX helpers ---------------------------------------------------
__device__ __forceinline__ uint smem_u32(const void* p) {
    uint a; asm("{ .reg .u64 t; cvta.to.shared.u64 t, %1; cvt.u32.u64 %0, t; }"
                : "=r"(a) : "l"(p));
    return a;
}

#define LDSM4(r0, r1, r2, r3, addr) \
    asm volatile("ldmatrix.sync.aligned.m8n8.x4.shared.b16 {%0,%1,%2,%3}, [%4];" \
        : "=r"(r0), "=r"(r1), "=r"(r2), "=r"(r3) : "r"(addr))

#define LDSM2(r0, r1, addr) \
    asm volatile("ldmatrix.sync.aligned.m8n8.x2.shared.b16 {%0,%1}, [%2];" \
        : "=r"(r0), "=r"(r1) : "r"(addr))

#define MMA16816(d, a, b) \
    asm volatile("mma.sync.aligned.m16n8k16.row.col.f32.f16.f16.f32 " \
        "{%0,%1,%2,%3}, {%4,%5,%6,%7}, {%8,%9}, {%0,%1,%2,%3};" \
        : "+f"((d)[0]), "+f"((d)[1]), "+f"((d)[2]), "+f"((d)[3]) \
        : "r"((a)[0]), "r"((a)[1]), "r"((a)[2]), "r"((a)[3]), \
          "r"((b)[0]), "r"((b)[1]))

// fp32 pair -> fp16x2 (a in low half)
__device__ __forceinline__ uint packh2(float a, float b) {
    __half2 h2 = __floats2half2_rn(a, b);
    return *reinterpret_cast<uint*>(&h2);
}

// MUFU.TANH-based activations: 1 MUFU each
__device__ __forceinline__ float ftanh_(float v) {
    float y; asm("tanh.approx.f32 %0, %1;" : "=f"(y) : "f"(v));
    return y;
}
__device__ __forceinline__ float fsigmoid(float v) {
    float y; asm("tanh.approx.f32 %0, %1;" : "=f"(y) : "f"(v*0.5f));
    return fmaf(0.5f, y, 0.5f);
}

// ---------------- main kernel: HMMA LSTM, single-pass fp16 ----------------------
__global__ void __launch_bounds__(128) lstm_hmma_kernel(
    const float* __restrict__ pm25,
    const float* __restrict__ feature,
    float* __restrict__ out)
{
    extern __shared__ char smem[];
    const uint sb = smem_u32(smem);
    const int tid = threadIdx.x;
    const int w = tid >> 5, lane = tid & 31;

    // stage B + vectors
    {
        const uint4* s = (const uint4*)g_B;
        uint4* d = (uint4*)(smem + SM_BHI);
        #pragma unroll
        for (int i = 0; i < 10; i++) d[i*128 + tid] = s[i*128 + tid];
    }
    if (tid < NHID) ((float*)(smem + SM_WOUT))[tid] = g_WOUT[tid];
    if (tid == 0)   *(float*)(smem + SM_BOUT) = g_BOUT[0];
    {
        uint4 z = make_uint4(0,0,0,0);
        #pragma unroll
        for (int kc = 6; kc < 10; kc++)
            ((uint4*)(smem + SM_AHI))[kc*128 + tid] = z;   // h=0
    }
    __syncthreads();

    // per-thread row state (thread = row for I/O, A-pack, pred)
    const int r = blockIdx.x*128 + tid;
    const int b = r / NC;
    const int c = r - b*NC;

    float xn[NHIST];
    #pragma unroll
    for (int t = 0; t < NHIST; t++) xn[t] = pm25[(size_t)r*NHIST + t];
    // c-state: cell (row', j) owned by the thread whose d-regs produce it
    float cst[32];
    #pragma unroll
    for (int i = 0; i < 32; i++) cst[i] = 0.0f;

    const float* fptr = feature + (((size_t)b*SEQ + NHIST)*NC + c)*NF;
    float* optr = out + ((size_t)b*NPRED)*NC + c;

    const float* sW  = (const float*)(smem + SM_WOUT);
    const float boutv = *(const float*)(smem + SM_BOUT);
    float* hbuf = (float*)(smem + SM_HBUF);

    // ldmatrix lane base addresses
    const uint rowA   = (uint)(w<<5) + (lane & 7) + (((lane >> 3) & 1) << 3);
    const uint aHiB   = sb + SM_AHI + rowA*16 + ((uint)(lane >> 4) & 1)*2048;
    const uint bBase  = sb + SM_BHI + (uint)(lane & 7)*16 + (((uint)(lane >> 3) & 1))*2048;

    // epilogue cell coordinates for this lane
    const int q = lane & 3;
    const int rbase = (w<<5) + (lane>>2);   // + mt*16 + rh*8

    #pragma unroll 1
    for (int s = 0; s < NPRED; s++) {
        // ---- build v = [xn | feat | 1(bias) | 0pad] fp16 ----
        float ft[NF];
        #pragma unroll
        for (int f = 0; f < NF; f++) ft[f] = fptr[f];
        fptr += (size_t)NC*NF;

        uint vh[24];
        #pragma unroll
        for (int p = 0; p < 12; p++) vh[p] = packh2(xn[2*p], xn[2*p+1]);
        #pragma unroll
        for (int p = 0; p < 8; p++) vh[12+p] = packh2(ft[2*p], ft[2*p+1]);
        vh[20] = packh2(ft[16], 1.0f);                // k40 = feat16, k41 = 1.0 (bias col)
        vh[21] = vh[22] = vh[23] = 0u;

        #pragma unroll
        for (int kc = 0; kc < 6; kc++)
            ((uint4*)(smem + SM_AHI))[kc*128 + tid] =
                make_uint4(vh[4*kc], vh[4*kc+1], vh[4*kc+2], vh[4*kc+3]);
        __syncwarp();

        // ---- hoisted A fragment loads (shared across all 16 n-tiles) ----
        uint afh[2][5][4];
        #pragma unroll
        for (int mt = 0; mt < 2; mt++)
            #pragma unroll
            for (int kt = 0; kt < 5; kt++)
                LDSM4(afh[mt][kt][0], afh[mt][kt][1], afh[mt][kt][2], afh[mt][kt][3],
                      aHiB + mt*256 + kt*4096);

        // ---- per n-tile: 4 gate-planes accumulate, then shuffle-free epilogue ----
        #pragma unroll
        for (int nt = 0; nt < 4; nt++) {
            float d[4][2][4];
            #pragma unroll
            for (int g = 0; g < 4; g++) {
                #pragma unroll
                for (int mt = 0; mt < 2; mt++)
                    #pragma unroll
                    for (int i = 0; i < 4; i++) d[g][mt][i] = 0.f;
                #pragma unroll
                for (int kt = 0; kt < 5; kt++) {
                    uint bf[2];
                    LDSM2(bf[0], bf[1], bBase + g*512 + nt*128 + kt*4096);
                    MMA16816(d[g][0], afh[0][kt], bf);
                    MMA16816(d[g][1], afh[1][kt], bf);
                }
            }
            // cells: rows rbase + mt*16 + rh*8 ; j = nt*8 + 2q + t
            #pragma unroll
            for (int mt = 0; mt < 2; mt++)
                #pragma unroll
                for (int rh = 0; rh < 2; rh++)
                    #pragma unroll
                    for (int t = 0; t < 2; t++) {
                        const int dreg = 2*rh + t;
                        const float zi = d[0][mt][dreg];
                        const float zf = d[1][mt][dreg];
                        const float zg = d[2][mt][dreg];
                        const float zo = d[3][mt][dreg];
                        const int ci = ((nt*2 + mt)*2 + rh)*2 + t;
                        const float cn = fmaf(fsigmoid(zf), cst[ci],
                                              fsigmoid(zi)*ftanh_(zg));
                        cst[ci] = cn;
                        const float hvv = fsigmoid(zo) * ftanh_(cn);
                        const int row = rbase + (mt<<4) + (rh<<3);
                        const int jj  = (nt<<3) + (q<<1) + t;
                        hbuf[row*33 + jj] = hvv;
                    }
        }
        __syncwarp();

        // ---- per-thread: gather own row's h, pred, pack h into A for next step ----
        float pred = boutv;
        uint hh[16];
        #pragma unroll
        for (int p = 0; p < 16; p++) {
            const float h0 = hbuf[tid*33 + 2*p];
            const float h1 = hbuf[tid*33 + 2*p + 1];
            pred = fmaf(sW[2*p],   h0, pred);
            pred = fmaf(sW[2*p+1], h1, pred);
            hh[p] = packh2(h0, h1);
        }
        #pragma unroll
        for (int kc = 0; kc < 4; kc++)
            ((uint4*)(smem + SM_AHI))[(6+kc)*128 + tid] =
                make_uint4(hh[4*kc], hh[4*kc+1], hh[4*kc+2], hh[4*kc+3]);

        optr[(size_t)s*NC] = pred;
        #pragma unroll
        for (int t = 0; t < NHIST-1; t++) xn[t] = xn[t+1];
        xn[NHIST-1] = pred;
        __syncwarp();
    }
}

// ---------------- launch --------------------------------------------------------
extern "C" void kernel_launch(void* const* d_in, const int* in_sizes, int n_in,
                              void* d_out, int out_size)
{
    const float* pm25    = (const float*)d_in[0];
    const float* feature = (const float*)d_in[1];
    // d_in[2] time_feature: unused
    const float* Win  = (const float*)d_in[3];
    const float* bin  = (const float*)d_in[4];
    const float* Wih  = (const float*)d_in[5];
    const float* Whh  = (const float*)d_in[6];
    const float* bih  = (const float*)d_in[7];
    const float* bhh  = (const float*)d_in[8];
    const float* Wout = (const float*)d_in[9];
    const float* bout = (const float*)d_in[10];
    float* out = (float*)d_out;

    cudaFuncSetAttribute(lstm_hmma_kernel,
                         cudaFuncAttributeMaxDynamicSharedMemorySize, SM_SIZE);

    prep1<<<21, 256>>>(Win, bin, Wih, bih, bhh, Wout, bout);
    prep2<<<40, 256>>>(Whh);
    lstm_hmma_kernel<<<GRID, 128, SM_SIZE>>>(pm25, feature, out);
}